// round 15
// baseline (speedup 1.0000x reference)
#include <cuda_runtime.h>
#include <cuda_fp16.h>
#include <cstdint>

#define MAXN 50000
#define MAXE 800000
#define MAXEA (MAXE + MAXN)
#define HC 256
#define HEADS 4
#define HID 64
#define INCH 16

// ---------------- scratch (static device globals; no allocation) ----------------
__device__ __align__(16) float  g_bufB[MAXN * HC];            // layer-1 output activations
__device__ __align__(16) __half g_h16[MAXN * HC];             // layer-2 H in fp16 (gather feed)
__device__ __align__(16) float g_agg[MAXN * HEADS * INCH];
__device__ __align__(16) float g_dsum[MAXN * HEADS];
__device__ __align__(16) float g_asrc[MAXN * HEADS];
__device__ __align__(16) float g_adst[MAXN * HEADS];
__device__ __align__(16) float g_proj[INCH * HEADS * 2];
__device__ int g_csr_src[MAXEA];
__device__ int g_counts[MAXN];
__device__ int g_cursor[MAXN];
__device__ int g_offs[MAXN + 1];
__device__ int g_bsums[64];
__device__ int g_boffs[65];
__device__ int g_is64;

// ---------------- helpers ----------------
__device__ __forceinline__ float elu(float x) { return x > 0.f ? x : (__expf(x) - 1.f); }

__device__ __forceinline__ void load_edge(const void* ei, int E, int e, int& src, int& dst) {
    if (g_is64) {
        const long long* p = (const long long*)ei;
        src = (int)p[e];
        dst = (int)p[E + e];
    } else {
        const int* p = (const int*)ei;
        src = p[e];
        dst = p[E + e];
    }
}

// ---------------- init: zero counts/cursors + dtype detect (block 0) ----------------
__global__ void init_kernel(int* a, int* b, int n, const int* ei_words) {
    int i = blockIdx.x * blockDim.x + threadIdx.x;
    if (i < n) { a[i] = 0; b[i] = 0; }
    if (blockIdx.x == 0) {
        __shared__ int any_nonzero;
        if (threadIdx.x == 0) any_nonzero = 0;
        __syncthreads();
        for (int k = threadIdx.x; k < 512; k += blockDim.x)
            if (ei_words[2 * k + 1] != 0) any_nonzero = 1;
        __syncthreads();
        if (threadIdx.x == 0) g_is64 = any_nonzero ? 0 : 1;
    }
}

// ---------------- CSR construction ----------------
__global__ void count_kernel(const void* __restrict__ ei, int E, int EA, int* __restrict__ counts) {
    int e = blockIdx.x * blockDim.x + threadIdx.x;
    if (e >= EA) return;
    int src, dst;
    if (e >= E) { dst = e - E; }
    else        { load_edge(ei, E, e, src, dst); }
    atomicAdd(&counts[dst], 1);
}

__global__ void blocksum_kernel(const int* __restrict__ counts, int* __restrict__ bsums, int N) {
    __shared__ int sh[256];
    int base = blockIdx.x * 1024;
    int s = 0;
    for (int i = threadIdx.x; i < 1024; i += 256) {
        int idx = base + i;
        if (idx < N) s += counts[idx];
    }
    sh[threadIdx.x] = s;
    __syncthreads();
    for (int o = 128; o; o >>= 1) {
        if (threadIdx.x < o) sh[threadIdx.x] += sh[threadIdx.x + o];
        __syncthreads();
    }
    if (threadIdx.x == 0) bsums[blockIdx.x] = sh[0];
}

__global__ void bscan_kernel(const int* __restrict__ bsums, int* __restrict__ boffs, int nb) {
    __shared__ int sh[256];
    int v = (threadIdx.x < nb) ? bsums[threadIdx.x] : 0;
    sh[threadIdx.x] = v;
    __syncthreads();
    for (int o = 1; o < 256; o <<= 1) {
        int t = (threadIdx.x >= o) ? sh[threadIdx.x - o] : 0;
        __syncthreads();
        sh[threadIdx.x] += t;
        __syncthreads();
    }
    if (threadIdx.x < nb) boffs[threadIdx.x + 1] = sh[threadIdx.x];
    if (threadIdx.x == 0) boffs[0] = 0;
}

__global__ void scan3_kernel(const int* __restrict__ counts, const int* __restrict__ boffs,
                             int* __restrict__ offs, int N, int nb) {
    __shared__ int sh[256];
    int base = blockIdx.x * 1024 + threadIdx.x * 4;
    int c[4];
    int s = 0;
#pragma unroll
    for (int t = 0; t < 4; t++) {
        int idx = base + t;
        c[t] = (idx < N) ? counts[idx] : 0;
        s += c[t];
    }
    sh[threadIdx.x] = s;
    __syncthreads();
    for (int o = 1; o < 256; o <<= 1) {
        int t = (threadIdx.x >= o) ? sh[threadIdx.x - o] : 0;
        __syncthreads();
        sh[threadIdx.x] += t;
        __syncthreads();
    }
    int run = boffs[blockIdx.x] + (threadIdx.x ? sh[threadIdx.x - 1] : 0);
#pragma unroll
    for (int t = 0; t < 4; t++) {
        int idx = base + t;
        if (idx < N) offs[idx] = run;
        run += c[t];
    }
    if (blockIdx.x == 0 && threadIdx.x == 0) offs[N] = boffs[nb];
}

__global__ void fill_kernel(const void* __restrict__ ei, int E, int EA,
                            const int* __restrict__ offs, int* __restrict__ cursor,
                            int* __restrict__ csr_src) {
    int e = blockIdx.x * blockDim.x + threadIdx.x;
    if (e >= EA) return;
    int src, dst;
    if (e >= E) { src = e - E; dst = src; }
    else        { load_edge(ei, E, e, src, dst); }
    int p = offs[dst] + atomicAdd(&cursor[dst], 1);
    csr_src[p] = src;
}

// ---------------- layer 1 prep: proj[k][h][{s,d}] ----------------
__global__ void prep1_kernel(const float* __restrict__ W1, const float* __restrict__ as1,
                             const float* __restrict__ ad1, float* __restrict__ proj) {
    int t = threadIdx.x;
    if (t >= INCH * HEADS) return;
    int k = t >> 2, h = t & 3;
    float ss = 0.f, sd = 0.f;
#pragma unroll
    for (int c = 0; c < HID; c++) {
        float w = W1[k * HC + h * HID + c];
        ss = fmaf(w, as1[h * HID + c], ss);
        sd = fmaf(w, ad1[h * HID + c], sd);
    }
    proj[(k * HEADS + h) * 2 + 0] = ss;
    proj[(k * HEADS + h) * 2 + 1] = sd;
}

// ---------------- layer 1 attention scalars straight from x ----------------
__global__ void alpha1_kernel(const float* __restrict__ x, const float* __restrict__ proj,
                              float* __restrict__ asrc, float* __restrict__ adst, int N) {
    __shared__ float pr[INCH * HEADS * 2];
    for (int i = threadIdx.x; i < INCH * HEADS * 2; i += blockDim.x) pr[i] = proj[i];
    __syncthreads();
    int t = blockIdx.x * blockDim.x + threadIdx.x;
    if (t >= N * HEADS) return;
    int n = t >> 2, h = t & 3;
    const float* xr = x + (size_t)n * INCH;
    float ss = 0.f, sd = 0.f;
#pragma unroll
    for (int k = 0; k < INCH; k++) {
        float v = xr[k];
        ss = fmaf(v, pr[(k * HEADS + h) * 2 + 0], ss);
        sd = fmaf(v, pr[(k * HEADS + h) * 2 + 1], sd);
    }
    asrc[t] = ss;
    adst[t] = sd;
}

// ---------------- layer 1 gather in input space ----------------
__global__ void gather1_kernel(const int* __restrict__ offs, const int* __restrict__ csr_src,
                               const float* __restrict__ asrc, const float* __restrict__ adst,
                               const float* __restrict__ x, float* __restrict__ agg,
                               float* __restrict__ dsum, int N) {
    int n = (blockIdx.x * blockDim.x + threadIdx.x) >> 5;
    if (n >= N) return;
    int lane = threadIdx.x & 31;
    int h = lane >> 3;
    int k2 = (lane & 7) * 2;
    float adh = __ldg(&adst[n * 4 + h]);
    int beg = offs[n], end = offs[n + 1];

    float a0 = 0.f, a1 = 0.f, ds = 0.f;
#pragma unroll 2
    for (int i = beg; i < end; i++) {
        int src = __ldg(&csr_src[i]);
        float e = __ldg(&asrc[src * 4 + h]) + adh;
        float wv = __expf(e > 0.f ? e : 0.2f * e);
        ds += wv;
        float2 xv = *(const float2*)(x + (size_t)src * INCH + k2);
        a0 = fmaf(wv, xv.x, a0);
        a1 = fmaf(wv, xv.y, a1);
    }
    float2* op = (float2*)(agg + (size_t)n * 64 + h * INCH + k2);
    *op = make_float2(a0, a1);
    if ((lane & 7) == 0) dsum[n * 4 + h] = ds;
}

// ---------------- layer 1 post ----------------
__global__ void post1_kernel(const float* __restrict__ agg, const float* __restrict__ dsum,
                             const float* __restrict__ W1, const float* __restrict__ b1,
                             float* __restrict__ out, int N) {
    __shared__ float ag[16 * 64];
    __shared__ float dsm[16 * 4];
    int n0 = blockIdx.x * 16;
    int j = threadIdx.x;
    int h = j >> 6;
    for (int i = threadIdx.x; i < 16 * 64; i += 256) {
        int node = n0 + i / 64;
        ag[i] = (node < N) ? agg[(size_t)n0 * 64 + i] : 0.f;
    }
    if (threadIdx.x < 64) {
        int node = n0 + threadIdx.x / 4;
        dsm[threadIdx.x] = (node < N) ? dsum[n0 * 4 + threadIdx.x] : 1.f;
    }
    __syncthreads();

    float wreg[INCH];
#pragma unroll
    for (int k = 0; k < INCH; k++) wreg[k] = W1[k * HC + j];
    float bj = b1[j];

    for (int i = 0; i < 16; i++) {
        int node = n0 + i;
        if (node >= N) break;
        const float* ar = ag + i * 64 + h * INCH;
        float s = 0.f;
#pragma unroll
        for (int k = 0; k < INCH; k++) s = fmaf(ar[k], wreg[k], s);
        float v = s / dsm[i * 4 + h] + bj;
        out[(size_t)node * HC + j] = elu(v);
    }
}

// ---------------- layer-2 transform + FUSED alpha: H16 = fp16(X@W2), asrc/adst from fp32 acc ----
// 256 threads = output columns, 64 nodes per block (32 pairs), f32x2 packed FMA.
__global__ void transform2_kernel(const float* __restrict__ X, const float* __restrict__ W,
                                  const float* __restrict__ a_s, const float* __restrict__ a_d,
                                  __half* __restrict__ H16, float* __restrict__ asrc,
                                  float* __restrict__ adst, int N) {
    constexpr int K = 256;
    constexpr int NPB = 64;
    constexpr int PAIRS = NPB / 2;
    constexpr int RSTR = PAIRS + 1;
    constexpr int KC = 128;
    __shared__ unsigned long long xs2[KC * RSTR];
    __shared__ float red[8][PAIRS][4];   // per warp: {lo_s, lo_d, hi_s, hi_d}

    int n0 = blockIdx.x * NPB;
    int j = threadIdx.x;
    int warp = threadIdx.x >> 5, lane = threadIdx.x & 31;

    unsigned long long acc[PAIRS];
#pragma unroll
    for (int p = 0; p < PAIRS; p++) acc[p] = 0ull;

    for (int kc0 = 0; kc0 < K; kc0 += KC) {
        __syncthreads();
        for (int idx = threadIdx.x; idx < NPB * KC; idx += 256) {
            int i = idx / KC, kk = idx % KC;
            int node = n0 + i;
            float v = (node < N) ? X[(size_t)node * K + kc0 + kk] : 0.f;
            ((float*)xs2)[(kk * RSTR + (i >> 1)) * 2 + (i & 1)] = v;
        }
        __syncthreads();

        for (int kk = 0; kk < KC; kk++) {
            float wv = W[(kc0 + kk) * HC + j];
            unsigned long long wv2;
            asm("mov.b64 %0, {%1, %1};" : "=l"(wv2) : "f"(wv));
            const unsigned long long* row = xs2 + kk * RSTR;
#pragma unroll
            for (int p = 0; p < PAIRS; p++) {
                asm("fma.rn.f32x2 %0, %1, %2, %0;" : "+l"(acc[p]) : "l"(row[p]), "l"(wv2));
            }
        }
    }

    float asj = a_s[j], adj = a_d[j];

#pragma unroll
    for (int p = 0; p < PAIRS; p++) {
        float lo, hi;
        asm("mov.b64 {%0, %1}, %2;" : "=f"(lo), "=f"(hi) : "l"(acc[p]));
        int na = n0 + 2 * p, nb = na + 1;
        if (na < N) H16[(size_t)na * HC + j] = __float2half_rn(lo);
        if (nb < N) H16[(size_t)nb * HC + j] = __float2half_rn(hi);
        // alpha contributions, reduce within warp (head = warp>>1, 2 warps per head)
        float v0 = lo * asj, v1 = lo * adj, v2 = hi * asj, v3 = hi * adj;
#pragma unroll
        for (int o = 16; o; o >>= 1) {
            v0 += __shfl_down_sync(0xffffffffu, v0, o);
            v1 += __shfl_down_sync(0xffffffffu, v1, o);
            v2 += __shfl_down_sync(0xffffffffu, v2, o);
            v3 += __shfl_down_sync(0xffffffffu, v3, o);
        }
        if (lane == 0) {
            red[warp][p][0] = v0;
            red[warp][p][1] = v1;
            red[warp][p][2] = v2;
            red[warp][p][3] = v3;
        }
    }
    __syncthreads();
    // combine the two warps of each head: thread t -> (node_local = t>>2, h = t&3)
    {
        int node_local = threadIdx.x >> 2, h = threadIdx.x & 3;
        int node = n0 + node_local;
        if (node < N) {
            int p = node_local >> 1;
            int off = (node_local & 1) ? 2 : 0;
            float s = red[2 * h][p][off]     + red[2 * h + 1][p][off];
            float d = red[2 * h][p][off + 1] + red[2 * h + 1][p][off + 1];
            asrc[node * 4 + h] = s;
            adst[node * 4 + h] = d;
        }
    }
}

// ---------------- layer-2 FUSED gather + head-mean + bias + ELU + classifier ----------------
// one warp per node; lane: head h=lane>>3, chunk g=lane&7 (channels g*8..g*8+8 within head)
__global__ void gather2_kernel(const int* __restrict__ offs, const int* __restrict__ csr_src,
                               const float* __restrict__ asrc, const float* __restrict__ adst,
                               const __half* __restrict__ H16, const float* __restrict__ b2,
                               const float* __restrict__ Wc, const float* __restrict__ bc,
                               float* __restrict__ out, int N) {
    __shared__ float sWc[HID * 8];
    for (int i = threadIdx.x; i < HID * 8; i += blockDim.x) sWc[i] = Wc[i];
    __syncthreads();

    int n = (blockIdx.x * blockDim.x + threadIdx.x) >> 5;
    if (n >= N) return;
    int lane = threadIdx.x & 31;
    int h = lane >> 3;
    int g = lane & 7;
    int cbase = lane * 8;
    float adh = __ldg(&adst[n * 4 + h]);
    int beg = offs[n], end = offs[n + 1];

    float acc[8];
#pragma unroll
    for (int j = 0; j < 8; j++) acc[j] = 0.f;
    float dsm = 0.f;

#pragma unroll 2
    for (int i = beg; i < end; i++) {
        int src = __ldg(&csr_src[i]);
        float e = __ldg(&asrc[src * 4 + h]) + adh;
        float wv = __expf(e > 0.f ? e : 0.2f * e);
        dsm += wv;
        float4 raw = *(const float4*)(H16 + (size_t)src * HC + cbase);  // 8 halves
        float2 f0 = __half22float2(*(const __half2*)&raw.x);
        float2 f1 = __half22float2(*(const __half2*)&raw.y);
        float2 f2 = __half22float2(*(const __half2*)&raw.z);
        float2 f3 = __half22float2(*(const __half2*)&raw.w);
        acc[0] = fmaf(wv, f0.x, acc[0]);
        acc[1] = fmaf(wv, f0.y, acc[1]);
        acc[2] = fmaf(wv, f1.x, acc[2]);
        acc[3] = fmaf(wv, f1.y, acc[3]);
        acc[4] = fmaf(wv, f2.x, acc[4]);
        acc[5] = fmaf(wv, f2.y, acc[5]);
        acc[6] = fmaf(wv, f3.x, acc[6]);
        acc[7] = fmaf(wv, f3.y, acc[7]);
    }

    float inv = 1.f / dsm;
    float feat[8];
#pragma unroll
    for (int j = 0; j < 8; j++) {
        float v = acc[j] * inv;
        // sum across 4 heads (lanes differing in bits 3,4)
        v += __shfl_xor_sync(0xffffffffu, v, 8);
        v += __shfl_xor_sync(0xffffffffu, v, 16);
        feat[j] = elu(0.25f * v + __ldg(&b2[g * 8 + j]));
    }

    float po[8];
#pragma unroll
    for (int o = 0; o < 8; o++) po[o] = 0.f;
#pragma unroll
    for (int j = 0; j < 8; j++) {
        const float* wr = sWc + (g * 8 + j) * 8;
#pragma unroll
        for (int o = 0; o < 8; o++) po[o] = fmaf(feat[j], wr[o], po[o]);
    }
    // sum across the 8 chunks (lanes differing in bits 0..2)
#pragma unroll
    for (int o = 0; o < 8; o++) {
        po[o] += __shfl_xor_sync(0xffffffffu, po[o], 1);
        po[o] += __shfl_xor_sync(0xffffffffu, po[o], 2);
        po[o] += __shfl_xor_sync(0xffffffffu, po[o], 4);
    }
    if (lane == 0) {
        float4* op = (float4*)(out + (size_t)n * 8);
        op[0] = make_float4(po[0] + bc[0], po[1] + bc[1], po[2] + bc[2], po[3] + bc[3]);
        op[1] = make_float4(po[4] + bc[4], po[5] + bc[5], po[6] + bc[6], po[7] + bc[7]);
    }
}

// ---------------- launch ----------------
extern "C" void kernel_launch(void* const* d_in, const int* in_sizes, int n_in,
                              void* d_out, int out_size) {
    const float* x   = (const float*)d_in[0];
    const void*  ei  = d_in[1];
    const float* W1  = (const float*)d_in[2];
    const float* as1 = (const float*)d_in[3];
    const float* ad1 = (const float*)d_in[4];
    const float* b1  = (const float*)d_in[5];
    const float* W2  = (const float*)d_in[6];
    const float* as2 = (const float*)d_in[7];
    const float* ad2 = (const float*)d_in[8];
    const float* b2  = (const float*)d_in[9];
    const float* Wc  = (const float*)d_in[10];
    const float* bc  = (const float*)d_in[11];
    float* out = (float*)d_out;

    int N  = in_sizes[0] / 16;
    int E  = in_sizes[1] / 2;
    int EA = E + N;
    int nb = (N + 1023) / 1024;

    float *bufB, *agg, *dsum, *asrc, *adst, *proj;
    __half* h16;
    int *csr_src, *counts, *cursor, *offs, *bsums, *boffs;
    cudaGetSymbolAddress((void**)&bufB,    g_bufB);
    cudaGetSymbolAddress((void**)&h16,     g_h16);
    cudaGetSymbolAddress((void**)&agg,     g_agg);
    cudaGetSymbolAddress((void**)&dsum,    g_dsum);
    cudaGetSymbolAddress((void**)&asrc,    g_asrc);
    cudaGetSymbolAddress((void**)&adst,    g_adst);
    cudaGetSymbolAddress((void**)&proj,    g_proj);
    cudaGetSymbolAddress((void**)&csr_src, g_csr_src);
    cudaGetSymbolAddress((void**)&counts,  g_counts);
    cudaGetSymbolAddress((void**)&cursor,  g_cursor);
    cudaGetSymbolAddress((void**)&offs,    g_offs);
    cudaGetSymbolAddress((void**)&bsums,   g_bsums);
    cudaGetSymbolAddress((void**)&boffs,   g_boffs);

    const int B = 256;
    int gridT      = (N + 63) / 64;
    int gridAlpha1 = (N * HEADS + B - 1) / B;
    int gridEdge   = (EA + B - 1) / B;
    int gridGather = (N * 32 + B - 1) / B;
    int gridPost1  = (N + 15) / 16;
    int gridZeroN  = (N + B - 1) / B;

    // ----- init + CSR structure -----
    init_kernel<<<gridZeroN, B>>>(counts, cursor, N, (const int*)ei);
    count_kernel<<<gridEdge, B>>>(ei, E, EA, counts);
    blocksum_kernel<<<nb, B>>>(counts, bsums, N);
    bscan_kernel<<<1, B>>>(bsums, boffs, nb);
    scan3_kernel<<<nb, B>>>(counts, boffs, offs, N, nb);
    fill_kernel<<<gridEdge, B>>>(ei, E, EA, offs, cursor, csr_src);

    // ----- layer 1 (input-space aggregation) -----
    prep1_kernel<<<1, 64>>>(W1, as1, ad1, proj);
    alpha1_kernel<<<gridAlpha1, B>>>(x, proj, asrc, adst, N);
    gather1_kernel<<<gridGather, B>>>(offs, csr_src, asrc, adst, x, agg, dsum, N);
    post1_kernel<<<gridPost1, B>>>(agg, dsum, W1, b1, bufB, N);

    // ----- layer 2 (transform + fused alpha; fused gather/epilogue/classifier) -----
    transform2_kernel<<<gridT, B>>>(bufB, W2, as2, ad2, h16, asrc, adst, N);
    gather2_kernel<<<gridGather, B>>>(offs, csr_src, asrc, adst, h16, b2, Wc, bc, out, N);
}